// round 2
// baseline (speedup 1.0000x reference)
#include <cuda_runtime.h>
#include <math.h>

// Problem constants
#define Bc 4
#define Sc 4096
#define Dc 128
#define Kc 64
#define Vc 128
#define BSc (Bc*Sc)          // 16384 tokens
#define OUTC (Dc + Vc)       // 256

// ---------------------------------------------------------------------------
// Scratch (device globals; no allocation allowed)
// ---------------------------------------------------------------------------
__device__ float g_Q [BSc * Kc];            // 4 MB   [b*S+s][k]
__device__ float g_Kp[BSc * Kc];            // 4 MB
__device__ float g_Vp[BSc * Vc];            // 8 MB
__device__ float g_E [(size_t)Bc * Sc * Sc];// 256 MB  exp(scores), causal region
__device__ float g_denom[BSc];              // column sums per (b, j)

// ---------------------------------------------------------------------------
// Kernel 0: zero denominators (atomics accumulate into them each launch)
// ---------------------------------------------------------------------------
__global__ void zden_kernel() {
    int i = blockIdx.x * 256 + threadIdx.x;
    if (i < BSc) g_denom[i] = 0.0f;
}

// ---------------------------------------------------------------------------
// Kernel 1: projections  Q = xWq^T + bq ; K = xWk^T + bk ; V = xWv^T + bv
// grid (BS/64, 4): y = 0:Q, 1:K, 2:V[:,0:64], 3:V[:,64:128]
// block tile: 64 tokens x 64 outputs, reduce over D=128
// ---------------------------------------------------------------------------
__global__ void proj_kernel(const float* __restrict__ x,
                            const float* __restrict__ Wq, const float* __restrict__ bq,
                            const float* __restrict__ Wk, const float* __restrict__ bk,
                            const float* __restrict__ Wv, const float* __restrict__ bv) {
    const int g  = blockIdx.y;
    const int t0 = blockIdx.x * 64;

    const float* W;  const float* bias;  float* out;  int ostride, ncol0;
    if (g == 0)      { W = Wq;           bias = bq;      out = g_Q;  ostride = Kc; ncol0 = 0;  }
    else if (g == 1) { W = Wk;           bias = bk;      out = g_Kp; ostride = Kc; ncol0 = 0;  }
    else if (g == 2) { W = Wv;           bias = bv;      out = g_Vp; ostride = Vc; ncol0 = 0;  }
    else             { W = Wv + 64 * Dc; bias = bv + 64; out = g_Vp; ostride = Vc; ncol0 = 64; }

    __shared__ float As[64][17];
    __shared__ float Ws[64][17];

    const int tid = threadIdx.x;
    const int ty = tid / 16, tx = tid % 16;

    float acc[4][4] = {};

    const int li = tid / 4;          // row 0..63 for loads
    const int lk = (tid % 4) * 4;    // k offset 0,4,8,12

    for (int kk = 0; kk < Dc; kk += 16) {
        float4 a4 = *(const float4*)&x[(size_t)(t0 + li) * Dc + kk + lk];
        As[li][lk+0] = a4.x; As[li][lk+1] = a4.y; As[li][lk+2] = a4.z; As[li][lk+3] = a4.w;
        float4 w4 = *(const float4*)&W[(size_t)li * Dc + kk + lk];
        Ws[li][lk+0] = w4.x; Ws[li][lk+1] = w4.y; Ws[li][lk+2] = w4.z; Ws[li][lk+3] = w4.w;
        __syncthreads();
        #pragma unroll
        for (int k = 0; k < 16; k++) {
            float a[4], b[4];
            #pragma unroll
            for (int r = 0; r < 4; r++) a[r] = As[ty*4+r][k];
            #pragma unroll
            for (int c = 0; c < 4; c++) b[c] = Ws[tx*4+c][k];
            #pragma unroll
            for (int r = 0; r < 4; r++)
                #pragma unroll
                for (int c = 0; c < 4; c++)
                    acc[r][c] += a[r] * b[c];
        }
        __syncthreads();
    }

    #pragma unroll
    for (int r = 0; r < 4; r++) {
        #pragma unroll
        for (int c = 0; c < 4; c++) {
            int col = tx*4 + c;
            out[(size_t)(t0 + ty*4 + r) * ostride + ncol0 + col] = acc[r][c] + bias[col];
        }
    }
}

// ---------------------------------------------------------------------------
// Kernel 2: E[q,j] = exp(Q.K^T / 8) on causal tiles; accumulate column sums.
// grid (2080, B): linear index over lower-triangular 64x64 tile pairs (qt>=jt)
// ---------------------------------------------------------------------------
__global__ void scores_kernel() {
    const int b   = blockIdx.y;
    const int lin = blockIdx.x;

    // triangular index -> (qt, jt), qt >= jt
    int qt = (int)((sqrtf(8.0f * (float)lin + 1.0f) - 1.0f) * 0.5f);
    while ((qt + 1) * (qt + 2) / 2 <= lin) qt++;
    while (qt * (qt + 1) / 2 > lin) qt--;
    const int jt = lin - qt * (qt + 1) / 2;

    const int q0 = qt * 64, j0 = jt * 64;
    const float* Qb = g_Q  + (size_t)b * Sc * Kc;
    const float* Kb = g_Kp + (size_t)b * Sc * Kc;

    __shared__ float Qs[64][17];
    __shared__ float Ks[64][17];
    __shared__ float csum[64];

    const int tid = threadIdx.x;
    const int ty = tid / 16, tx = tid % 16;
    if (tid < 64) csum[tid] = 0.0f;

    float acc[4][4] = {};
    const int li = tid / 4;
    const int lk = (tid % 4) * 4;

    for (int kk = 0; kk < Kc; kk += 16) {
        float4 q4 = *(const float4*)&Qb[(size_t)(q0 + li) * Kc + kk + lk];
        Qs[li][lk+0] = q4.x; Qs[li][lk+1] = q4.y; Qs[li][lk+2] = q4.z; Qs[li][lk+3] = q4.w;
        float4 k4 = *(const float4*)&Kb[(size_t)(j0 + li) * Kc + kk + lk];
        Ks[li][lk+0] = k4.x; Ks[li][lk+1] = k4.y; Ks[li][lk+2] = k4.z; Ks[li][lk+3] = k4.w;
        __syncthreads();
        #pragma unroll
        for (int k = 0; k < 16; k++) {
            float a[4], bb[4];
            #pragma unroll
            for (int r = 0; r < 4; r++) a[r]  = Qs[ty*4+r][k];
            #pragma unroll
            for (int c = 0; c < 4; c++) bb[c] = Ks[tx*4+c][k];
            #pragma unroll
            for (int r = 0; r < 4; r++)
                #pragma unroll
                for (int c = 0; c < 4; c++)
                    acc[r][c] += a[r] * bb[c];
        }
        __syncthreads();
    }

    float* Eb = g_E + (size_t)b * Sc * Sc;
    #pragma unroll
    for (int r = 0; r < 4; r++) {
        const int q = q0 + ty*4 + r;
        float e[4];
        float colacc[4];
        #pragma unroll
        for (int c = 0; c < 4; c++) {
            const int j = j0 + tx*4 + c;
            float s = acc[r][c] * 0.125f;       // 1/sqrt(K), K=64
            e[c] = (j <= q) ? __expf(s) : 0.0f; // causal mask
            colacc[c] = e[c];
        }
        float4 ev = make_float4(e[0], e[1], e[2], e[3]);
        *(float4*)&Eb[(size_t)q * Sc + j0 + tx*4] = ev;
        #pragma unroll
        for (int c = 0; c < 4; c++)
            atomicAdd(&csum[tx*4 + c], colacc[c]);
    }
    __syncthreads();
    if (tid < 64)
        atomicAdd(&g_denom[b * Sc + j0 + tid], csum[tid]);
}

// ---------------------------------------------------------------------------
// Kernel 3: out[:, :, 0:128] = x ; out[:, :, 128:256] = 0
// ---------------------------------------------------------------------------
__global__ void concat_kernel(const float* __restrict__ x, float* __restrict__ out) {
    size_t idx = (size_t)blockIdx.x * 256 + threadIdx.x;   // < BSc*OUTC
    int c = (int)(idx % OUTC);
    size_t t = idx / OUTC;
    out[idx] = (c < Dc) ? x[t * Dc + c] : 0.0f;
}

// ---------------------------------------------------------------------------
// Kernel 4: attention += E @ (V / denom[j])   (causal, j-split + atomicAdd)
// grid (544, B). Each block: 64 q-rows x 128 v-cols, j-chunk of 256.
// ---------------------------------------------------------------------------
#define JCHUNK 256
__global__ void attn_kernel(float* __restrict__ out) {
    const int b   = blockIdx.y;
    const int lin = blockIdx.x;

    // linear -> (qt, chunk): chunks(qt) = ceil((qt+1)/4)
    int qt = 0, base = 0;
    for (;;) {
        int c = (qt + 4) >> 2;
        if (lin < base + c) break;
        base += c; qt++;
    }
    const int chunk = lin - base;
    const int q0 = qt * 64;
    const int j_begin = chunk * JCHUNK;
    const int j_end   = min(q0 + 64, j_begin + JCHUNK);   // exclusive, mult of 16

    const float* Eb = g_E  + (size_t)b * Sc * Sc;
    const float* Vb = g_Vp + (size_t)b * Sc * Vc;
    const float* db = g_denom + b * Sc;

    __shared__ float Es[64][17];
    __shared__ float Ws[16][128];

    const int tid = threadIdx.x;
    const int ty = tid / 16, tx = tid % 16;

    float acc[4][8] = {};

    const int li = tid / 4;          // E row
    const int lk = (tid % 4) * 4;    // E j offset
    const int jr = tid >> 4;         // W row 0..15
    const int cb = (tid & 15) * 8;   // W col base

    for (int j0 = j_begin; j0 < j_end; j0 += 16) {
        float4 e4 = *(const float4*)&Eb[(size_t)(q0 + li) * Sc + j0 + lk];
        Es[li][lk+0] = e4.x; Es[li][lk+1] = e4.y; Es[li][lk+2] = e4.z; Es[li][lk+3] = e4.w;

        float inv = 1.0f / db[j0 + jr];
        const float* vp = &Vb[(size_t)(j0 + jr) * Vc + cb];
        float4 w0 = *(const float4*)vp;
        float4 w1 = *(const float4*)(vp + 4);
        Ws[jr][cb+0] = w0.x * inv; Ws[jr][cb+1] = w0.y * inv;
        Ws[jr][cb+2] = w0.z * inv; Ws[jr][cb+3] = w0.w * inv;
        Ws[jr][cb+4] = w1.x * inv; Ws[jr][cb+5] = w1.y * inv;
        Ws[jr][cb+6] = w1.z * inv; Ws[jr][cb+7] = w1.w * inv;
        __syncthreads();

        #pragma unroll
        for (int k = 0; k < 16; k++) {
            float a[4];
            #pragma unroll
            for (int r = 0; r < 4; r++) a[r] = Es[ty*4+r][k];
            float4 b0 = *(const float4*)&Ws[k][tx*8];
            float4 b1 = *(const float4*)&Ws[k][tx*8 + 4];
            #pragma unroll
            for (int r = 0; r < 4; r++) {
                acc[r][0] += a[r]*b0.x; acc[r][1] += a[r]*b0.y;
                acc[r][2] += a[r]*b0.z; acc[r][3] += a[r]*b0.w;
                acc[r][4] += a[r]*b1.x; acc[r][5] += a[r]*b1.y;
                acc[r][6] += a[r]*b1.z; acc[r][7] += a[r]*b1.w;
            }
        }
        __syncthreads();
    }

    #pragma unroll
    for (int r = 0; r < 4; r++) {
        size_t row = (size_t)(b * Sc + q0 + ty*4 + r) * OUTC + Dc + tx*8;
        #pragma unroll
        for (int c = 0; c < 8; c++)
            atomicAdd(&out[row + c], acc[r][c]);
    }
}

// ---------------------------------------------------------------------------
// Launch
// ---------------------------------------------------------------------------
extern "C" void kernel_launch(void* const* d_in, const int* in_sizes, int n_in,
                              void* d_out, int out_size) {
    const float* x  = (const float*)d_in[0];
    const float* Wq = (const float*)d_in[1];
    const float* bq = (const float*)d_in[2];
    const float* Wk = (const float*)d_in[3];
    const float* bk = (const float*)d_in[4];
    const float* Wv = (const float*)d_in[5];
    const float* bv = (const float*)d_in[6];
    float* out = (float*)d_out;

    zden_kernel<<<(BSc + 255) / 256, 256>>>();
    proj_kernel<<<dim3(BSc / 64, 4), 256>>>(x, Wq, bq, Wk, bk, Wv, bv);
    scores_kernel<<<dim3(2080, Bc), 256>>>();          // 64*65/2 causal tiles
    concat_kernel<<<(BSc * OUTC) / 256, 256>>>(x, out);
    attn_kernel<<<dim3(544, Bc), 256>>>(out);          // sum ceil((qt+1)/4)
}

// round 5
// speedup vs baseline: 2.1708x; 2.1708x over previous
#include <cuda_runtime.h>
#include <cuda_bf16.h>
#include <cuda_fp16.h>
#include <cstdint>

#define Bc 4
#define Sc 4096
#define Dc 128
#define Kc 64
#define Vc 128
#define BSc (Bc*Sc)
#define OUTC 256

// ---------------- scratch ----------------
__device__ __nv_bfloat16 g_Qs[(size_t)BSc * 128];      // [hi64 | lo64] per token
__device__ __nv_bfloat16 g_Ks[(size_t)BSc * 128];
__device__ float         g_Vp[(size_t)BSc * Vc];
__device__ __half        g_E[(size_t)Bc * Sc * Sc];    // 134 MB, exp(scores), causal zeros
__device__ __half        g_Vthi[(size_t)Bc * Vc * Sc]; // [b][v][s]
__device__ __half        g_Vtlo[(size_t)Bc * Vc * Sc];
__device__ float         g_denom[BSc];

// ---------------- mma wrappers (sm_80+ PTX, compiles under compute_100) ----
__device__ __forceinline__ void mma_bf16(float* d, const uint32_t* a, const uint32_t* b) {
    asm volatile("mma.sync.aligned.m16n8k16.row.col.f32.bf16.bf16.f32 "
        "{%0,%1,%2,%3}, {%4,%5,%6,%7}, {%8,%9}, {%0,%1,%2,%3};"
        : "+f"(d[0]), "+f"(d[1]), "+f"(d[2]), "+f"(d[3])
        : "r"(a[0]), "r"(a[1]), "r"(a[2]), "r"(a[3]), "r"(b[0]), "r"(b[1]));
}
__device__ __forceinline__ void mma_f16(float* d, const uint32_t* a, const uint32_t* b) {
    asm volatile("mma.sync.aligned.m16n8k16.row.col.f32.f16.f16.f32 "
        "{%0,%1,%2,%3}, {%4,%5,%6,%7}, {%8,%9}, {%0,%1,%2,%3};"
        : "+f"(d[0]), "+f"(d[1]), "+f"(d[2]), "+f"(d[3])
        : "r"(a[0]), "r"(a[1]), "r"(a[2]), "r"(a[3]), "r"(b[0]), "r"(b[1]));
}
__device__ __forceinline__ uint32_t pack_bf(__nv_bfloat16 a, __nv_bfloat16 b) {
    __nv_bfloat162 t; t.x = a; t.y = b;
    return *reinterpret_cast<uint32_t*>(&t);
}
__device__ __forceinline__ uint32_t pack_h(__half a, __half b) {
    __half2 t; t.x = a; t.y = b;
    return *reinterpret_cast<uint32_t*>(&t);
}

// ---------------- kernel 0: zero denom ----------------
__global__ void zden_kernel() {
    int i = blockIdx.x * 256 + threadIdx.x;
    if (i < BSc) g_denom[i] = 0.0f;
}

// ---------------- kernel 1: projections ----------------
__global__ void proj_kernel(const float* __restrict__ x,
                            const float* __restrict__ Wq, const float* __restrict__ bq,
                            const float* __restrict__ Wk, const float* __restrict__ bk,
                            const float* __restrict__ Wv, const float* __restrict__ bv) {
    const int g  = blockIdx.y;
    const int t0 = blockIdx.x * 64;
    const float* W; const float* bias; int ncol0 = 0;
    if (g == 0)      { W = Wq;           bias = bq;      }
    else if (g == 1) { W = Wk;           bias = bk;      }
    else if (g == 2) { W = Wv;           bias = bv;      }
    else             { W = Wv + 64 * Dc; bias = bv + 64; ncol0 = 64; }

    __shared__ float As[64][17];
    __shared__ float Ws[64][17];
    const int tid = threadIdx.x;
    const int ty = tid / 16, tx = tid % 16;
    float acc[4][4] = {};
    const int li = tid / 4, lk = (tid % 4) * 4;

    for (int kk = 0; kk < Dc; kk += 16) {
        float4 a4 = *(const float4*)&x[(size_t)(t0 + li) * Dc + kk + lk];
        As[li][lk+0] = a4.x; As[li][lk+1] = a4.y; As[li][lk+2] = a4.z; As[li][lk+3] = a4.w;
        float4 w4 = *(const float4*)&W[(size_t)li * Dc + kk + lk];
        Ws[li][lk+0] = w4.x; Ws[li][lk+1] = w4.y; Ws[li][lk+2] = w4.z; Ws[li][lk+3] = w4.w;
        __syncthreads();
        #pragma unroll
        for (int k = 0; k < 16; k++) {
            float a[4], b[4];
            #pragma unroll
            for (int r = 0; r < 4; r++) a[r] = As[ty*4+r][k];
            #pragma unroll
            for (int c = 0; c < 4; c++) b[c] = Ws[tx*4+c][k];
            #pragma unroll
            for (int r = 0; r < 4; r++)
                #pragma unroll
                for (int c = 0; c < 4; c++) acc[r][c] += a[r] * b[c];
        }
        __syncthreads();
    }
    if (g <= 1) {
        __nv_bfloat16* outb = (g == 0) ? g_Qs : g_Ks;
        #pragma unroll
        for (int r = 0; r < 4; r++) {
            __nv_bfloat16* rp = outb + (size_t)(t0 + ty*4 + r) * 128;
            #pragma unroll
            for (int c = 0; c < 4; c++) {
                int col = tx*4 + c;
                float v = acc[r][c] + bias[col];
                __nv_bfloat16 h = __float2bfloat16(v);
                rp[col] = h;
                rp[64 + col] = __float2bfloat16(v - __bfloat162float(h));
            }
        }
    } else {
        #pragma unroll
        for (int r = 0; r < 4; r++)
            #pragma unroll
            for (int c = 0; c < 4; c++)
                g_Vp[(size_t)(t0 + ty*4 + r) * Vc + ncol0 + tx*4 + c] = acc[r][c] + bias[tx*4 + c];
    }
}

// ---------------- kernel 2: scores (mma.sync bf16 split) + denom ----------
// CTA: 256 thr (8 warps 4x2), tile 128q x 128j. K_eff = 3 x 64.
#define SCQ 1024
#define SCK (1024 + 34816)
#define SC_SMEM (1024 + 2*34816)    // 70656; fp32 stage (128x129) overlays at 1024

__global__ __launch_bounds__(256) void scores_kernel() {
    extern __shared__ char smem[];
    const int tid = threadIdx.x;
    const int wid = tid >> 5, lane = tid & 31;
    const int grp = lane >> 2, qr = lane & 3;
    const int wm = wid >> 1, wn = wid & 1;
    const int b = blockIdx.y;

    int lin = blockIdx.x, qt = 0, base = 0;
    while (base + qt + 1 <= lin) { base += qt + 1; qt++; }
    const int jt = lin - base;
    const int q0 = qt * 128, j0 = jt * 128;

    {   // load Q/K tiles: 128 rows x 256B, smem row stride 272B
        const char* srcQ = (const char*)(g_Qs + (size_t)(b * Sc + q0) * 128);
        const char* srcK = (const char*)(g_Ks + (size_t)(b * Sc + j0) * 128);
        for (int idx = tid; idx < 2048; idx += 256) {
            int r = idx >> 4, ch = idx & 15;
            *(uint4*)(smem + SCQ + r*272 + ch*16) = *(const uint4*)(srcQ + r*256 + ch*16);
            *(uint4*)(smem + SCK + r*272 + ch*16) = *(const uint4*)(srcK + r*256 + ch*16);
        }
    }
    __syncthreads();

    float acc[2][8][4] = {};
    const char* Qb = smem + SCQ;
    const char* Kb = smem + SCK;
    const int aT[3] = {0, 1, 0}, bT[3] = {0, 0, 1};   // hi*hi + lo*hi + hi*lo

    #pragma unroll
    for (int t = 0; t < 3; t++) {
        #pragma unroll
        for (int ks = 0; ks < 4; ks++) {
            const int kA = aT[t]*64 + ks*16, kB = bT[t]*64 + ks*16;
            uint32_t afr[2][4];
            #pragma unroll
            for (int ma = 0; ma < 2; ma++) {
                const char* p = Qb + (wm*32 + ma*16 + grp)*272 + (kA + qr*2)*2;
                afr[ma][0] = *(const uint32_t*)p;
                afr[ma][1] = *(const uint32_t*)(p + 8*272);
                afr[ma][2] = *(const uint32_t*)(p + 16);
                afr[ma][3] = *(const uint32_t*)(p + 8*272 + 16);
            }
            uint32_t bfr[8][2];
            #pragma unroll
            for (int na = 0; na < 8; na++) {
                const char* p = Kb + (wn*64 + na*8 + grp)*272 + (kB + qr*2)*2;
                bfr[na][0] = *(const uint32_t*)p;
                bfr[na][1] = *(const uint32_t*)(p + 16);
            }
            #pragma unroll
            for (int ma = 0; ma < 2; ma++)
                #pragma unroll
                for (int na = 0; na < 8; na++)
                    mma_bf16(acc[ma][na], afr[ma], bfr[na]);
        }
    }

    // exp + causal mask in regs
    #pragma unroll
    for (int ma = 0; ma < 2; ma++)
        #pragma unroll
        for (int na = 0; na < 8; na++)
            #pragma unroll
            for (int c = 0; c < 4; c++) {
                int q = q0 + wm*32 + ma*16 + grp + ((c >= 2) ? 8 : 0);
                int j = j0 + wn*64 + na*8 + qr*2 + (c & 1);
                float s = acc[ma][na][c] * 0.125f;
                acc[ma][na][c] = (j <= q) ? __expf(s) : 0.0f;
            }
    __syncthreads();    // everyone done with Q/K smem

    float* stage = (float*)(smem + 1024);   // [128][129]
    #pragma unroll
    for (int ma = 0; ma < 2; ma++) {
        const int r0 = wm*32 + ma*16 + grp;
        #pragma unroll
        for (int na = 0; na < 8; na++) {
            const int c0 = wn*64 + na*8 + qr*2;
            stage[r0*129 + c0]       = acc[ma][na][0];
            stage[r0*129 + c0 + 1]   = acc[ma][na][1];
            stage[(r0+8)*129 + c0]     = acc[ma][na][2];
            stage[(r0+8)*129 + c0 + 1] = acc[ma][na][3];
        }
    }
    __syncthreads();

    // write E (fp16): thread -> (row, half); 64 halfs = 8 x uint4
    {
        const int r = tid >> 1, h = tid & 1;
        const int q = q0 + r;
        uint32_t packs[32];
        #pragma unroll
        for (int k = 0; k < 32; k++) {
            float f0 = stage[r*129 + h*64 + 2*k];
            float f1 = stage[r*129 + h*64 + 2*k + 1];
            packs[k] = pack_h(__float2half(f0), __float2half(f1));
        }
        uint4* dst = (uint4*)(g_E + (size_t)(b * Sc + q) * Sc + j0 + h*64);
        #pragma unroll
        for (int k = 0; k < 8; k++) dst[k] = ((uint4*)packs)[k];
    }
    // column sums -> denom
    if (tid < 128) {
        float s = 0.0f;
        #pragma unroll 8
        for (int r = 0; r < 128; r++) s += stage[r*129 + tid];
        atomicAdd(&g_denom[b * Sc + j0 + tid], s);
    }
}

// ---------------- kernel 3: vprep  Vt = split_fp16((V/denom)^T) ------------
__global__ void vprep_kernel() {
    __shared__ float tile[64][129];
    __shared__ float invs[64];
    const int b = blockIdx.y, s0 = blockIdx.x * 64, tid = threadIdx.x;
    if (tid < 64) invs[tid] = 1.0f / g_denom[b * Sc + s0 + tid];
    __syncthreads();
    for (int sl = 0; sl < 64; sl++)
        tile[sl][tid] = g_Vp[(size_t)(b * Sc + s0 + sl) * Vc + tid] * invs[sl];
    __syncthreads();
    uint32_t hp[32], lp[32];
    #pragma unroll
    for (int i = 0; i < 32; i++) {
        float v0 = tile[2*i][tid], v1 = tile[2*i+1][tid];
        __half h0 = __float2half(v0), h1 = __float2half(v1);
        hp[i] = pack_h(h0, h1);
        lp[i] = pack_h(__float2half(v0 - __half2float(h0)),
                       __float2half(v1 - __half2float(h1)));
    }
    uint4* dh = (uint4*)(g_Vthi + (size_t)(b * Vc + tid) * Sc + s0);
    uint4* dl = (uint4*)(g_Vtlo + (size_t)(b * Vc + tid) * Sc + s0);
    #pragma unroll
    for (int i = 0; i < 8; i++) { dh[i] = ((uint4*)hp)[i]; dl[i] = ((uint4*)lp)[i]; }
}

// ---------------- kernel 4: concat ----------------
__global__ void concat_kernel(const float* __restrict__ x, float* __restrict__ out) {
    size_t idx = (size_t)blockIdx.x * 256 + threadIdx.x;   // float4 index
    int c4 = (int)(idx & 63);
    size_t t = idx >> 6;
    float4 v = make_float4(0.f, 0.f, 0.f, 0.f);
    if (c4 < 32) v = ((const float4*)x)[t * 32 + c4];
    ((float4*)out)[idx] = v;
}

// ---------------- kernel 5: attn (mma.sync f16) ----------------------------
// CTA: 256 thr (8 warps 4x2), tile 128q x 128v, loop over <=4 j-tiles of 128.
#define AT_ES 0
#define AT_VH 34816
#define AT_VL 69632
#define AT_SMEM 104448

__global__ __launch_bounds__(256) void attn_kernel(float* __restrict__ out) {
    extern __shared__ char smem[];
    const int tid = threadIdx.x;
    const int wid = tid >> 5, lane = tid & 31;
    const int grp = lane >> 2, qr = lane & 3;
    const int wm = wid >> 1, wn = wid & 1;
    const int b = blockIdx.y;

    // decode (qt, group-of-4-jtiles): groups(qt) = ceil((qt+1)/4); sum = 144
    int lin = blockIdx.x, qt = 0, base = 0;
    for (;;) { int gq = (qt + 4) >> 2; if (lin < base + gq) break; base += gq; qt++; }
    const int g0 = (lin - base) * 4;
    const int g1 = min(qt + 1, g0 + 4);
    const int q0 = qt * 128;

    float acc[2][8][4] = {};

    for (int jt = g0; jt < g1; jt++) {
        const int j0 = jt * 128;
        for (int idx = tid; idx < 2048; idx += 256) {
            int r = idx >> 4, ch = idx & 15;
            *(uint4*)(smem + AT_ES + r*272 + ch*16) =
                *(const uint4*)((const char*)g_E + ((size_t)(b*Sc + q0 + r)*Sc + j0)*2 + ch*16);
            *(uint4*)(smem + AT_VH + r*272 + ch*16) =
                *(const uint4*)((const char*)g_Vthi + ((size_t)(b*Vc + r)*Sc + j0)*2 + ch*16);
            *(uint4*)(smem + AT_VL + r*272 + ch*16) =
                *(const uint4*)((const char*)g_Vtlo + ((size_t)(b*Vc + r)*Sc + j0)*2 + ch*16);
        }
        __syncthreads();

        #pragma unroll
        for (int ks = 0; ks < 8; ks++) {
            const int kb = ks * 16;
            uint32_t afr[2][4];
            #pragma unroll
            for (int ma = 0; ma < 2; ma++) {
                const char* p = smem + AT_ES + (wm*32 + ma*16 + grp)*272 + (kb + qr*2)*2;
                afr[ma][0] = *(const uint32_t*)p;
                afr[ma][1] = *(const uint32_t*)(p + 8*272);
                afr[ma][2] = *(const uint32_t*)(p + 16);
                afr[ma][3] = *(const uint32_t*)(p + 8*272 + 16);
            }
            uint32_t bh[8][2], bl[8][2];
            #pragma unroll
            for (int na = 0; na < 8; na++) {
                const char* ph = smem + AT_VH + (wn*64 + na*8 + grp)*272 + (kb + qr*2)*2;
                bh[na][0] = *(const uint32_t*)ph;
                bh[na][1] = *(const uint32_t*)(ph + 16);
                const char* pl = smem + AT_VL + (wn*64 + na*8 + grp)*272 + (kb + qr*2)*2;
                bl[na][0] = *(const uint32_t*)pl;
                bl[na][1] = *(const uint32_t*)(pl + 16);
            }
            #pragma unroll
            for (int ma = 0; ma < 2; ma++)
                #pragma unroll
                for (int na = 0; na < 8; na++) {
                    mma_f16(acc[ma][na], afr[ma], bh[na]);
                    mma_f16(acc[ma][na], afr[ma], bl[na]);
                }
        }
        __syncthreads();
    }

    // epilogue: atomic adds into out[:, 128:256]
    #pragma unroll
    for (int ma = 0; ma < 2; ma++) {
        const int r0 = q0 + wm*32 + ma*16 + grp;
        #pragma unroll
        for (int na = 0; na < 8; na++) {
            const int v0 = wn*64 + na*8 + qr*2;
            atomicAdd(&out[(size_t)(b*Sc + r0)*OUTC + Dc + v0],     acc[ma][na][0]);
            atomicAdd(&out[(size_t)(b*Sc + r0)*OUTC + Dc + v0 + 1], acc[ma][na][1]);
            atomicAdd(&out[(size_t)(b*Sc + r0 + 8)*OUTC + Dc + v0],     acc[ma][na][2]);
            atomicAdd(&out[(size_t)(b*Sc + r0 + 8)*OUTC + Dc + v0 + 1], acc[ma][na][3]);
        }
    }
}

// ---------------- launch ----------------
extern "C" void kernel_launch(void* const* d_in, const int* in_sizes, int n_in,
                              void* d_out, int out_size) {
    const float* x  = (const float*)d_in[0];
    const float* Wq = (const float*)d_in[1];
    const float* bq = (const float*)d_in[2];
    const float* Wk = (const float*)d_in[3];
    const float* bk = (const float*)d_in[4];
    const float* Wv = (const float*)d_in[5];
    const float* bv = (const float*)d_in[6];
    float* out = (float*)d_out;

    cudaFuncSetAttribute(scores_kernel, cudaFuncAttributeMaxDynamicSharedMemorySize, SC_SMEM);
    cudaFuncSetAttribute(attn_kernel,   cudaFuncAttributeMaxDynamicSharedMemorySize, AT_SMEM);

    zden_kernel<<<(BSc + 255) / 256, 256>>>();
    proj_kernel<<<dim3(BSc / 64, 4), 256>>>(x, Wq, bq, Wk, bk, Wv, bv);
    scores_kernel<<<dim3(528, Bc), 256, SC_SMEM>>>();
    vprep_kernel<<<dim3(Sc / 64, Bc), 128>>>();
    concat_kernel<<<(BSc * 64) / 256, 256>>>(x, out);
    attn_kernel<<<dim3(144, Bc), 256, AT_SMEM>>>(out);
}

// round 6
// speedup vs baseline: 3.1183x; 1.4365x over previous
#include <cuda_runtime.h>
#include <cuda_bf16.h>
#include <cuda_fp16.h>
#include <cstdint>

#define Bc 4
#define Sc 4096
#define Dc 128
#define Kc 64
#define Vc 128
#define BSc (Bc*Sc)
#define OUTC 256

// ---------------- scratch ----------------
__device__ __nv_bfloat16 g_Qs[(size_t)BSc * 128];      // [hi64 | lo64] per token
__device__ __nv_bfloat16 g_Ks[(size_t)BSc * 128];
__device__ float         g_Vp[(size_t)BSc * Vc];
__device__ __half        g_E[(size_t)Bc * Sc * Sc];    // 134 MB, exp(scores), causal zeros
__device__ __half        g_Vt[(size_t)Bc * Vc * Sc];   // [b][v][s], V/denom, fp16
__device__ float         g_denom[BSc];

// ---------------- PTX helpers ----------------
__device__ __forceinline__ uint32_t smem_u32(const void* p) {
    uint32_t a;
    asm("{ .reg .u64 t; cvta.to.shared.u64 t, %1; cvt.u32.u64 %0, t; }" : "=r"(a) : "l"(p));
    return a;
}
#define CP16(dst, src) \
    asm volatile("cp.async.cg.shared.global [%0], [%1], 16;" :: "r"(dst), "l"(src))
#define CP_WAIT() \
    asm volatile("cp.async.commit_group;\ncp.async.wait_group 0;" ::: "memory")
#define LDM_X4(d0, d1, d2, d3, a) \
    asm volatile("ldmatrix.sync.aligned.m8n8.x4.shared.b16 {%0,%1,%2,%3}, [%4];" \
        : "=r"(d0), "=r"(d1), "=r"(d2), "=r"(d3) : "r"(a))

__device__ __forceinline__ void mma_bf16(float* d, const uint32_t* a, const uint32_t* b) {
    asm volatile("mma.sync.aligned.m16n8k16.row.col.f32.bf16.bf16.f32 "
        "{%0,%1,%2,%3}, {%4,%5,%6,%7}, {%8,%9}, {%0,%1,%2,%3};"
        : "+f"(d[0]), "+f"(d[1]), "+f"(d[2]), "+f"(d[3])
        : "r"(a[0]), "r"(a[1]), "r"(a[2]), "r"(a[3]), "r"(b[0]), "r"(b[1]));
}
__device__ __forceinline__ void mma_f16(float* d, const uint32_t* a, const uint32_t* b) {
    asm volatile("mma.sync.aligned.m16n8k16.row.col.f32.f16.f16.f32 "
        "{%0,%1,%2,%3}, {%4,%5,%6,%7}, {%8,%9}, {%0,%1,%2,%3};"
        : "+f"(d[0]), "+f"(d[1]), "+f"(d[2]), "+f"(d[3])
        : "r"(a[0]), "r"(a[1]), "r"(a[2]), "r"(a[3]), "r"(b[0]), "r"(b[1]));
}
__device__ __forceinline__ uint32_t pack_h(__half a, __half b) {
    __half2 t; t.x = a; t.y = b;
    return *reinterpret_cast<uint32_t*>(&t);
}

// ---------------- kernel 0: zero denom ----------------
__global__ void zden_kernel() {
    int i = blockIdx.x * 256 + threadIdx.x;
    if (i < BSc) g_denom[i] = 0.0f;
}

// ---------------- kernel 1: projections ----------------
__global__ void proj_kernel(const float* __restrict__ x,
                            const float* __restrict__ Wq, const float* __restrict__ bq,
                            const float* __restrict__ Wk, const float* __restrict__ bk,
                            const float* __restrict__ Wv, const float* __restrict__ bv) {
    const int g  = blockIdx.y;
    const int t0 = blockIdx.x * 64;
    const float* W; const float* bias; int ncol0 = 0;
    if (g == 0)      { W = Wq;           bias = bq;      }
    else if (g == 1) { W = Wk;           bias = bk;      }
    else if (g == 2) { W = Wv;           bias = bv;      }
    else             { W = Wv + 64 * Dc; bias = bv + 64; ncol0 = 64; }

    __shared__ float As[64][17];
    __shared__ float Ws[64][17];
    const int tid = threadIdx.x;
    const int ty = tid / 16, tx = tid % 16;
    float acc[4][4] = {};
    const int li = tid / 4, lk = (tid % 4) * 4;

    for (int kk = 0; kk < Dc; kk += 16) {
        float4 a4 = *(const float4*)&x[(size_t)(t0 + li) * Dc + kk + lk];
        As[li][lk+0] = a4.x; As[li][lk+1] = a4.y; As[li][lk+2] = a4.z; As[li][lk+3] = a4.w;
        float4 w4 = *(const float4*)&W[(size_t)li * Dc + kk + lk];
        Ws[li][lk+0] = w4.x; Ws[li][lk+1] = w4.y; Ws[li][lk+2] = w4.z; Ws[li][lk+3] = w4.w;
        __syncthreads();
        #pragma unroll
        for (int k = 0; k < 16; k++) {
            float a[4], b[4];
            #pragma unroll
            for (int r = 0; r < 4; r++) a[r] = As[ty*4+r][k];
            #pragma unroll
            for (int c = 0; c < 4; c++) b[c] = Ws[tx*4+c][k];
            #pragma unroll
            for (int r = 0; r < 4; r++)
                #pragma unroll
                for (int c = 0; c < 4; c++) acc[r][c] += a[r] * b[c];
        }
        __syncthreads();
    }
    if (g <= 1) {
        __nv_bfloat16* outb = (g == 0) ? g_Qs : g_Ks;
        #pragma unroll
        for (int r = 0; r < 4; r++) {
            __nv_bfloat16* rp = outb + (size_t)(t0 + ty*4 + r) * 128;
            #pragma unroll
            for (int c = 0; c < 4; c++) {
                int col = tx*4 + c;
                float v = acc[r][c] + bias[col];
                __nv_bfloat16 h = __float2bfloat16(v);
                rp[col] = h;
                rp[64 + col] = __float2bfloat16(v - __bfloat162float(h));
            }
        }
    } else {
        #pragma unroll
        for (int r = 0; r < 4; r++)
            #pragma unroll
            for (int c = 0; c < 4; c++)
                g_Vp[(size_t)(t0 + ty*4 + r) * Vc + ncol0 + tx*4 + c] = acc[r][c] + bias[tx*4 + c];
    }
}

// ---------------- kernel 2: scores (mma + ldmatrix) + denom ----------------
// 256 thr (8 warps, 4x2), tile 128q x 128j, K_eff = 3 x 64 (split bf16).
#define SCQ 0
#define SCK 34816
#define SC_SMEM 69632   // fp16 stage [128][136] overlays [0, 34816)

__global__ __launch_bounds__(256) void scores_kernel() {
    extern __shared__ char smem[];
    const uint32_t sb = smem_u32(smem);
    const int tid = threadIdx.x;
    const int wid = tid >> 5, lane = tid & 31;
    const int grp = lane >> 2, qr = lane & 3;
    const int wm = wid >> 1, wn = wid & 1;
    const int b = blockIdx.y;

    int lin = blockIdx.x, qt = 0, base = 0;
    while (base + qt + 1 <= lin) { base += qt + 1; qt++; }
    const int jt = lin - base;
    const int q0 = qt * 128, j0 = jt * 128;

    {   // cp.async tile fill: 128 rows x 256B, smem stride 272
        const char* srcQ = (const char*)(g_Qs + (size_t)(b * Sc + q0) * 128);
        const char* srcK = (const char*)(g_Ks + (size_t)(b * Sc + j0) * 128);
        for (int idx = tid; idx < 2048; idx += 256) {
            int r = idx >> 4, ch = idx & 15;
            CP16(sb + SCQ + r*272 + ch*16, srcQ + r*256 + ch*16);
            CP16(sb + SCK + r*272 + ch*16, srcK + r*256 + ch*16);
        }
        CP_WAIT();
    }
    __syncthreads();

    float acc[2][8][4] = {};
    // per-thread ldmatrix base addresses
    const uint32_t aBase = sb + SCQ + (wm*32 + (lane & 15))*272 + (lane >> 4)*16;
    const uint32_t bBase = sb + SCK + (wn*64 + (lane & 15))*272 + (lane >> 4)*16;
    const int aT[3] = {0, 1, 0}, bT[3] = {0, 0, 1};   // hi*hi + lo*hi + hi*lo

    #pragma unroll
    for (int t = 0; t < 3; t++) {
        #pragma unroll
        for (int ks = 0; ks < 4; ks++) {
            const uint32_t aOff = (uint32_t)(aT[t]*128 + ks*32);
            const uint32_t bOff = (uint32_t)(bT[t]*128 + ks*32);
            uint32_t afr[2][4];
            #pragma unroll
            for (int ma = 0; ma < 2; ma++)
                LDM_X4(afr[ma][0], afr[ma][1], afr[ma][2], afr[ma][3],
                       aBase + ma*16*272 + aOff);
            uint32_t bfr[8][2];
            #pragma unroll
            for (int ng = 0; ng < 4; ng++) {
                uint32_t d0, d1, d2, d3;
                LDM_X4(d0, d1, d2, d3, bBase + ng*16*272 + bOff);
                bfr[2*ng][0]   = d0; bfr[2*ng][1]   = d2;
                bfr[2*ng+1][0] = d1; bfr[2*ng+1][1] = d3;
            }
            #pragma unroll
            for (int ma = 0; ma < 2; ma++)
                #pragma unroll
                for (int na = 0; na < 8; na++)
                    mma_bf16(acc[ma][na], afr[ma], bfr[na]);
        }
    }

    // exp + causal mask in regs
    #pragma unroll
    for (int ma = 0; ma < 2; ma++)
        #pragma unroll
        for (int na = 0; na < 8; na++)
            #pragma unroll
            for (int c = 0; c < 4; c++) {
                int q = q0 + wm*32 + ma*16 + grp + ((c >= 2) ? 8 : 0);
                int j = j0 + wn*64 + na*8 + qr*2 + (c & 1);
                float s = acc[ma][na][c] * 0.125f;
                acc[ma][na][c] = (j <= q) ? __expf(s) : 0.0f;
            }
    __syncthreads();    // done with Q/K smem

    __half* stage = (__half*)smem;   // [128][136]
    #pragma unroll
    for (int ma = 0; ma < 2; ma++) {
        const int r0 = wm*32 + ma*16 + grp;
        #pragma unroll
        for (int na = 0; na < 8; na++) {
            const int c0 = wn*64 + na*8 + qr*2;
            *(__half2*)&stage[r0*136 + c0] =
                __floats2half2_rn(acc[ma][na][0], acc[ma][na][1]);
            *(__half2*)&stage[(r0+8)*136 + c0] =
                __floats2half2_rn(acc[ma][na][2], acc[ma][na][3]);
        }
    }
    __syncthreads();

    // E write (coalesced uint4) from stage
    {
        const int r = tid >> 1, h = tid & 1;
        const uint4* src = (const uint4*)(smem + r*272 + h*128);
        uint4* dst = (uint4*)(g_E + (size_t)(b * Sc + q0 + r) * Sc + j0 + h*64);
        #pragma unroll
        for (int k = 0; k < 8; k++) dst[k] = src[k];
    }
    // column sums -> denom
    if (tid < 128) {
        float s = 0.0f;
        #pragma unroll 8
        for (int r = 0; r < 128; r++) s += __half2float(stage[r*136 + tid]);
        atomicAdd(&g_denom[b * Sc + j0 + tid], s);
    }
}

// ---------------- kernel 3: vprep  Vt = fp16((V/denom)^T) ------------------
// grid (128, 4), 256 thr, 32 s-rows per block
__global__ __launch_bounds__(256) void vprep_kernel() {
    __shared__ float tile[32][133];
    __shared__ float invs[32];
    const int b = blockIdx.y, s0 = blockIdx.x * 32, tid = threadIdx.x;
    if (tid < 32) invs[tid] = 1.0f / g_denom[b * Sc + s0 + tid];
    __syncthreads();
    #pragma unroll
    for (int i = 0; i < 16; i++) {
        int idx = tid + i * 256;
        int r = idx >> 7, c = idx & 127;
        tile[r][c] = g_Vp[(size_t)(b * Sc + s0 + r) * Vc + c] * invs[r];
    }
    __syncthreads();
    const int v = tid >> 1, h = tid & 1;
    uint32_t packs[8];
    #pragma unroll
    for (int k = 0; k < 8; k++)
        packs[k] = pack_h(__float2half(tile[h*16 + 2*k][v]),
                          __float2half(tile[h*16 + 2*k + 1][v]));
    uint4* dst = (uint4*)(g_Vt + (size_t)(b * Vc + v) * Sc + s0 + h*16);
    dst[0] = ((uint4*)packs)[0];
    dst[1] = ((uint4*)packs)[1];
}

// ---------------- kernel 4: concat ----------------
__global__ void concat_kernel(const float* __restrict__ x, float* __restrict__ out) {
    size_t idx = (size_t)blockIdx.x * 256 + threadIdx.x;   // float4 index
    int c4 = (int)(idx & 63);
    size_t t = idx >> 6;
    float4 v = make_float4(0.f, 0.f, 0.f, 0.f);
    if (c4 < 32) v = ((const float4*)x)[t * 32 + c4];
    ((float4*)out)[idx] = v;
}

// ---------------- kernel 5: attn (mma f16, hi-only V) ----------------------
// 256 thr (8 warps 4x2), tile 128q x 128v, up to 8 j-tiles of 128 per CTA.
#define AT_ES 0
#define AT_VH 34816
#define AT_SMEM 69632

__global__ __launch_bounds__(256) void attn_kernel(float* __restrict__ out) {
    extern __shared__ char smem[];
    const uint32_t sb = smem_u32(smem);
    const int tid = threadIdx.x;
    const int wid = tid >> 5, lane = tid & 31;
    const int grp = lane >> 2, qr = lane & 3;
    const int wm = wid >> 1, wn = wid & 1;
    const int b = blockIdx.y;

    // decode (qt, group-of-8-jtiles): groups(qt) = ceil((qt+1)/8); sum = 80
    int lin = blockIdx.x, qt = 0, base = 0;
    for (;;) { int gq = (qt + 8) >> 3; if (lin < base + gq) break; base += gq; qt++; }
    const int g0 = (lin - base) * 8;
    const int g1 = min(qt + 1, g0 + 8);
    const int q0 = qt * 128;

    float acc[2][8][4] = {};
    const uint32_t aBase = sb + AT_ES + (wm*32 + (lane & 15))*272 + (lane >> 4)*16;
    const uint32_t bBase = sb + AT_VH + (wn*64 + (lane & 15))*272 + (lane >> 4)*16;

    for (int jt = g0; jt < g1; jt++) {
        const int j0 = jt * 128;
        for (int idx = tid; idx < 2048; idx += 256) {
            int r = idx >> 4, ch = idx & 15;
            CP16(sb + AT_ES + r*272 + ch*16,
                 (const char*)g_E + ((size_t)(b*Sc + q0 + r)*Sc + j0)*2 + ch*16);
            CP16(sb + AT_VH + r*272 + ch*16,
                 (const char*)g_Vt + ((size_t)(b*Vc + r)*Sc + j0)*2 + ch*16);
        }
        CP_WAIT();
        __syncthreads();

        #pragma unroll
        for (int ks = 0; ks < 8; ks++) {
            const uint32_t kOff = (uint32_t)(ks * 32);
            uint32_t afr[2][4];
            #pragma unroll
            for (int ma = 0; ma < 2; ma++)
                LDM_X4(afr[ma][0], afr[ma][1], afr[ma][2], afr[ma][3],
                       aBase + ma*16*272 + kOff);
            uint32_t bfr[8][2];
            #pragma unroll
            for (int ng = 0; ng < 4; ng++) {
                uint32_t d0, d1, d2, d3;
                LDM_X4(d0, d1, d2, d3, bBase + ng*16*272 + kOff);
                bfr[2*ng][0]   = d0; bfr[2*ng][1]   = d2;
                bfr[2*ng+1][0] = d1; bfr[2*ng+1][1] = d3;
            }
            #pragma unroll
            for (int ma = 0; ma < 2; ma++)
                #pragma unroll
                for (int na = 0; na < 8; na++)
                    mma_f16(acc[ma][na], afr[ma], bfr[na]);
        }
        __syncthreads();
    }

    // epilogue: atomic adds into out[:, 128:256]
    #pragma unroll
    for (int ma = 0; ma < 2; ma++) {
        const int r0 = q0 + wm*32 + ma*16 + grp;
        #pragma unroll
        for (int na = 0; na < 8; na++) {
            const int v0 = wn*64 + na*8 + qr*2;
            atomicAdd(&out[(size_t)(b*Sc + r0)*OUTC + Dc + v0],     acc[ma][na][0]);
            atomicAdd(&out[(size_t)(b*Sc + r0)*OUTC + Dc + v0 + 1], acc[ma][na][1]);
            atomicAdd(&out[(size_t)(b*Sc + r0 + 8)*OUTC + Dc + v0],     acc[ma][na][2]);
            atomicAdd(&out[(size_t)(b*Sc + r0 + 8)*OUTC + Dc + v0 + 1], acc[ma][na][3]);
        }
    }
}

// ---------------- launch ----------------
extern "C" void kernel_launch(void* const* d_in, const int* in_sizes, int n_in,
                              void* d_out, int out_size) {
    const float* x  = (const float*)d_in[0];
    const float* Wq = (const float*)d_in[1];
    const float* bq = (const float*)d_in[2];
    const float* Wk = (const float*)d_in[3];
    const float* bk = (const float*)d_in[4];
    const float* Wv = (const float*)d_in[5];
    const float* bv = (const float*)d_in[6];
    float* out = (float*)d_out;

    cudaFuncSetAttribute(scores_kernel, cudaFuncAttributeMaxDynamicSharedMemorySize, SC_SMEM);
    cudaFuncSetAttribute(attn_kernel,   cudaFuncAttributeMaxDynamicSharedMemorySize, AT_SMEM);

    zden_kernel<<<(BSc + 255) / 256, 256>>>();
    proj_kernel<<<dim3(BSc / 64, 4), 256>>>(x, Wq, bq, Wk, bk, Wv, bv);
    scores_kernel<<<dim3(528, Bc), 256, SC_SMEM>>>();
    vprep_kernel<<<dim3(Sc / 32, Bc), 256>>>();
    concat_kernel<<<(BSc * 64) / 256, 256>>>(x, out);
    attn_kernel<<<dim3(80, Bc), 256, AT_SMEM>>>(out);
}

// round 7
// speedup vs baseline: 3.6107x; 1.1579x over previous
#include <cuda_runtime.h>
#include <cuda_bf16.h>
#include <cuda_fp16.h>
#include <cstdint>

#define Bc 4
#define Sc 4096
#define Dc 128
#define Kc 64
#define Vc 128
#define BSc (Bc*Sc)
#define OUTC 256

// ---------------- scratch ----------------
__device__ __nv_bfloat16 g_Qs[(size_t)BSc * 128];      // [hi64 | lo64] per token
__device__ __nv_bfloat16 g_Ks[(size_t)BSc * 128];
__device__ float         g_Vp[(size_t)BSc * Vc];
__device__ __half        g_E[(size_t)Bc * Sc * Sc];    // exp(scores), causal zeros
__device__ __half        g_Vt[(size_t)Bc * Vc * Sc];   // [b][v][s], V/denom, fp16
__device__ float         g_denom[BSc];

// ---------------- PTX helpers ----------------
__device__ __forceinline__ uint32_t smem_u32(const void* p) {
    uint32_t a;
    asm("{ .reg .u64 t; cvta.to.shared.u64 t, %1; cvt.u32.u64 %0, t; }" : "=r"(a) : "l"(p));
    return a;
}
#define CP16(dst, src) \
    asm volatile("cp.async.cg.shared.global [%0], [%1], 16;" :: "r"(dst), "l"(src))
#define CP_WAIT() \
    asm volatile("cp.async.commit_group;\ncp.async.wait_group 0;" ::: "memory")
#define LDM_X4(d0, d1, d2, d3, a) \
    asm volatile("ldmatrix.sync.aligned.m8n8.x4.shared.b16 {%0,%1,%2,%3}, [%4];" \
        : "=r"(d0), "=r"(d1), "=r"(d2), "=r"(d3) : "r"(a))

__device__ __forceinline__ void mma_bf16(float* d, const uint32_t* a, const uint32_t* b) {
    asm volatile("mma.sync.aligned.m16n8k16.row.col.f32.bf16.bf16.f32 "
        "{%0,%1,%2,%3}, {%4,%5,%6,%7}, {%8,%9}, {%0,%1,%2,%3};"
        : "+f"(d[0]), "+f"(d[1]), "+f"(d[2]), "+f"(d[3])
        : "r"(a[0]), "r"(a[1]), "r"(a[2]), "r"(a[3]), "r"(b[0]), "r"(b[1]));
}
__device__ __forceinline__ void mma_f16(float* d, const uint32_t* a, const uint32_t* b) {
    asm volatile("mma.sync.aligned.m16n8k16.row.col.f32.f16.f16.f32 "
        "{%0,%1,%2,%3}, {%4,%5,%6,%7}, {%8,%9}, {%0,%1,%2,%3};"
        : "+f"(d[0]), "+f"(d[1]), "+f"(d[2]), "+f"(d[3])
        : "r"(a[0]), "r"(a[1]), "r"(a[2]), "r"(a[3]), "r"(b[0]), "r"(b[1]));
}
__device__ __forceinline__ uint32_t pack_h(__half a, __half b) {
    __half2 t; t.x = a; t.y = b;
    return *reinterpret_cast<uint32_t*>(&t);
}
__device__ __forceinline__ uint32_t pack_b(__nv_bfloat16 a, __nv_bfloat16 b) {
    __nv_bfloat162 t; t.x = a; t.y = b;
    return *reinterpret_cast<uint32_t*>(&t);
}

// exp(s/8) computed as 2^(s*C): fp16x2 MUFU + fp32->fp16 residual correction.
// 2^t = 2^th * (1 + ln2*(t - th)); keeps error at fp16-rounding level.
__device__ __forceinline__ uint32_t exp2h2(float t0, float t1) {
    __half2 th = __floats2half2_rn(t0, t1);
    uint32_t thu = *reinterpret_cast<uint32_t*>(&th);
    uint32_t eu;
    asm("ex2.approx.f16x2 %0, %1;" : "=r"(eu) : "r"(thu));
    float tl0 = t0 - __half2float(__low2half(th));
    float tl1 = t1 - __half2float(__high2half(th));
    __half2 c = __floats2half2_rn(fmaf(0.6931472f, tl0, 1.0f),
                                  fmaf(0.6931472f, tl1, 1.0f));
    __half2 e = *reinterpret_cast<__half2*>(&eu);
    e = __hmul2(e, c);
    return *reinterpret_cast<uint32_t*>(&e);
}

// ---------------- kernel 1: projections (mma split-bf16) -------------------
// grid (BSc/128, 2). nh=0 -> [Q|K] (cols 0-63 / 64-127), nh=1 -> V.
#define PJ_A0 0
#define PJ_A1 34816
#define PJ_B0 69632
#define PJ_B1 104448
#define PJ_BIAS 139264
#define PJ_SMEM 139776

__global__ __launch_bounds__(256) void proj_kernel(
    const float* __restrict__ x,
    const float* __restrict__ Wq, const float* __restrict__ bq,
    const float* __restrict__ Wk, const float* __restrict__ bk,
    const float* __restrict__ Wv, const float* __restrict__ bv) {
    extern __shared__ char smem[];
    const uint32_t sb = smem_u32(smem);
    const int tid = threadIdx.x;
    const int wid = tid >> 5, lane = tid & 31;
    const int grp = lane >> 2, qr = lane & 3;
    const int wm = wid >> 1, wn = wid & 1;
    const int nh = blockIdx.y;
    const int t0 = blockIdx.x * 128;

    // fold denom zeroing in (runs before scores kernel)
    if (nh == 0) {
        int i = blockIdx.x * 256 + tid;
        if (i < BSc) g_denom[i] = 0.0f;
    }
    // bias to smem
    if (tid < 128) {
        float bvv = (nh == 0) ? ((tid < 64) ? bq[tid] : bk[tid - 64]) : bv[tid];
        ((float*)(smem + PJ_BIAS))[tid] = bvv;
    }

    // fill A (x rows) and B (W rows), split bf16, chunked by 64 K-cols
    #pragma unroll
    for (int i = 0; i < 16; i++) {
        int idx = tid + i * 256;              // 0..4095
        int r = idx >> 5, c4 = idx & 31;      // row, float4-col
        int ch = c4 >> 4, cc = c4 & 15;
        float4 a = *(const float4*)&x[(size_t)(t0 + r) * 128 + c4 * 4];
        __nv_bfloat16 h0 = __float2bfloat16(a.x), h1 = __float2bfloat16(a.y);
        __nv_bfloat16 h2 = __float2bfloat16(a.z), h3 = __float2bfloat16(a.w);
        uint2 hi = make_uint2(pack_b(h0, h1), pack_b(h2, h3));
        uint2 lo = make_uint2(
            pack_b(__float2bfloat16(a.x - __bfloat162float(h0)),
                   __float2bfloat16(a.y - __bfloat162float(h1))),
            pack_b(__float2bfloat16(a.z - __bfloat162float(h2)),
                   __float2bfloat16(a.w - __bfloat162float(h3))));
        char* ab = smem + (ch ? PJ_A1 : PJ_A0) + r * 272 + cc * 8;
        *(uint2*)ab = hi;
        *(uint2*)(ab + 128) = lo;

        const float* wsrc = (nh == 0)
            ? ((r < 64) ? (Wq + (size_t)r * 128) : (Wk + (size_t)(r - 64) * 128))
            : (Wv + (size_t)r * 128);
        float4 w = *(const float4*)&wsrc[c4 * 4];
        __nv_bfloat16 g0 = __float2bfloat16(w.x), g1 = __float2bfloat16(w.y);
        __nv_bfloat16 g2 = __float2bfloat16(w.z), g3 = __float2bfloat16(w.w);
        uint2 whi = make_uint2(pack_b(g0, g1), pack_b(g2, g3));
        uint2 wlo = make_uint2(
            pack_b(__float2bfloat16(w.x - __bfloat162float(g0)),
                   __float2bfloat16(w.y - __bfloat162float(g1))),
            pack_b(__float2bfloat16(w.z - __bfloat162float(g2)),
                   __float2bfloat16(w.w - __bfloat162float(g3))));
        char* bb = smem + (ch ? PJ_B1 : PJ_B0) + r * 272 + cc * 8;
        *(uint2*)bb = whi;
        *(uint2*)(bb + 128) = wlo;
    }
    __syncthreads();

    float acc[2][8][4] = {};
    const uint32_t aBase = sb + PJ_A0 + (wm*32 + (lane & 15))*272 + (lane >> 4)*16;
    const uint32_t bBase = sb + PJ_B0 + (wn*64 + (lane & 15))*272 + (lane >> 4)*16;
    const int aT[3] = {0, 1, 0}, bT[3] = {0, 0, 1};

    #pragma unroll
    for (int ch = 0; ch < 2; ch++) {
        #pragma unroll
        for (int t = 0; t < 3; t++) {
            #pragma unroll
            for (int ks = 0; ks < 4; ks++) {
                const uint32_t aOff = (uint32_t)(ch*34816 + aT[t]*128 + ks*32);
                const uint32_t bOff = (uint32_t)(ch*34816 + bT[t]*128 + ks*32);
                uint32_t afr[2][4];
                #pragma unroll
                for (int ma = 0; ma < 2; ma++)
                    LDM_X4(afr[ma][0], afr[ma][1], afr[ma][2], afr[ma][3],
                           aBase + ma*16*272 + aOff);
                uint32_t bfr[8][2];
                #pragma unroll
                for (int ng = 0; ng < 4; ng++) {
                    uint32_t d0, d1, d2, d3;
                    LDM_X4(d0, d1, d2, d3, bBase + ng*16*272 + bOff);
                    bfr[2*ng][0]   = d0; bfr[2*ng][1]   = d2;
                    bfr[2*ng+1][0] = d1; bfr[2*ng+1][1] = d3;
                }
                #pragma unroll
                for (int ma = 0; ma < 2; ma++)
                    #pragma unroll
                    for (int na = 0; na < 8; na++)
                        mma_bf16(acc[ma][na], afr[ma], bfr[na]);
            }
        }
    }
    __syncthreads();   // A tiles dead; overlay fp32 stage

    float* stage = (float*)smem;                 // [128][136]
    const float* biasS = (const float*)(smem + PJ_BIAS);
    #pragma unroll
    for (int ma = 0; ma < 2; ma++) {
        const int r0 = wm*32 + ma*16 + grp;
        #pragma unroll
        for (int na = 0; na < 8; na++) {
            const int c0 = wn*64 + na*8 + qr*2;
            stage[r0*136 + c0]     = acc[ma][na][0] + biasS[c0];
            stage[r0*136 + c0 + 1] = acc[ma][na][1] + biasS[c0 + 1];
            stage[(r0+8)*136 + c0]     = acc[ma][na][2] + biasS[c0];
            stage[(r0+8)*136 + c0 + 1] = acc[ma][na][3] + biasS[c0 + 1];
        }
    }
    __syncthreads();

    const int r = tid >> 1, h = tid & 1;
    if (nh == 0) {
        // h=0 -> Q (cols 0..63), h=1 -> K (cols 64..127); write split bf16 rows
        uint32_t hp[32], lp[32];
        #pragma unroll
        for (int k = 0; k < 32; k++) {
            float v0 = stage[r*136 + h*64 + 2*k];
            float v1 = stage[r*136 + h*64 + 2*k + 1];
            __nv_bfloat16 b0 = __float2bfloat16(v0), b1 = __float2bfloat16(v1);
            hp[k] = pack_b(b0, b1);
            lp[k] = pack_b(__float2bfloat16(v0 - __bfloat162float(b0)),
                           __float2bfloat16(v1 - __bfloat162float(b1)));
        }
        __nv_bfloat16* dstrow = (h == 0 ? g_Qs : g_Ks) + (size_t)(t0 + r) * 128;
        uint4* dh = (uint4*)dstrow;
        uint4* dl = (uint4*)(dstrow + 64);
        #pragma unroll
        for (int k = 0; k < 8; k++) { dh[k] = ((uint4*)hp)[k]; dl[k] = ((uint4*)lp)[k]; }
    } else {
        #pragma unroll
        for (int k = 0; k < 16; k++) {
            float4 v = *(const float4*)&stage[r*136 + h*64 + 4*k];
            *(float4*)&g_Vp[(size_t)(t0 + r) * 128 + h*64 + 4*k] = v;
        }
    }
}

// ---------------- kernel 2: scores (mma + ex2.f16x2) + denom ---------------
#define SCQ 0
#define SCK 34816
#define SC_SMEM 69632   // fp16 stage [128][136] overlays [0, 34816)

__global__ __launch_bounds__(256) void scores_kernel() {
    extern __shared__ char smem[];
    const uint32_t sb = smem_u32(smem);
    const int tid = threadIdx.x;
    const int wid = tid >> 5, lane = tid & 31;
    const int grp = lane >> 2, qr = lane & 3;
    const int wm = wid >> 1, wn = wid & 1;
    const int b = blockIdx.y;

    int lin = blockIdx.x, qt = 0, base = 0;
    while (base + qt + 1 <= lin) { base += qt + 1; qt++; }
    const int jt = lin - base;
    const int q0 = qt * 128, j0 = jt * 128;

    {   // cp.async tile fill: 128 rows x 256B, smem stride 272
        const char* srcQ = (const char*)(g_Qs + (size_t)(b * Sc + q0) * 128);
        const char* srcK = (const char*)(g_Ks + (size_t)(b * Sc + j0) * 128);
        for (int idx = tid; idx < 2048; idx += 256) {
            int r = idx >> 4, ch = idx & 15;
            CP16(sb + SCQ + r*272 + ch*16, srcQ + r*256 + ch*16);
            CP16(sb + SCK + r*272 + ch*16, srcK + r*256 + ch*16);
        }
        CP_WAIT();
    }
    __syncthreads();

    float acc[2][8][4] = {};
    const uint32_t aBase = sb + SCQ + (wm*32 + (lane & 15))*272 + (lane >> 4)*16;
    const uint32_t bBase = sb + SCK + (wn*64 + (lane & 15))*272 + (lane >> 4)*16;
    const int aT[3] = {0, 1, 0}, bT[3] = {0, 0, 1};

    #pragma unroll
    for (int t = 0; t < 3; t++) {
        #pragma unroll
        for (int ks = 0; ks < 4; ks++) {
            const uint32_t aOff = (uint32_t)(aT[t]*128 + ks*32);
            const uint32_t bOff = (uint32_t)(bT[t]*128 + ks*32);
            uint32_t afr[2][4];
            #pragma unroll
            for (int ma = 0; ma < 2; ma++)
                LDM_X4(afr[ma][0], afr[ma][1], afr[ma][2], afr[ma][3],
                       aBase + ma*16*272 + aOff);
            uint32_t bfr[8][2];
            #pragma unroll
            for (int ng = 0; ng < 4; ng++) {
                uint32_t d0, d1, d2, d3;
                LDM_X4(d0, d1, d2, d3, bBase + ng*16*272 + bOff);
                bfr[2*ng][0]   = d0; bfr[2*ng][1]   = d2;
                bfr[2*ng+1][0] = d1; bfr[2*ng+1][1] = d3;
            }
            #pragma unroll
            for (int ma = 0; ma < 2; ma++)
                #pragma unroll
                for (int na = 0; na < 8; na++)
                    mma_bf16(acc[ma][na], afr[ma], bfr[na]);
        }
    }
    __syncthreads();    // done with Q/K smem

    // epilogue: E = 2^(s*C) via ex2.f16x2 (+ residual correction), to stage
    const float C = 0.18033688011112042f;   // 0.125 * log2(e)
    __half* stage = (__half*)smem;          // [128][136]
    #pragma unroll
    for (int ma = 0; ma < 2; ma++) {
        const int r0 = wm*32 + ma*16 + grp;
        const int qlo = q0 + r0, qhi = qlo + 8;
        #pragma unroll
        for (int na = 0; na < 8; na++) {
            const int c0 = wn*64 + na*8 + qr*2;
            const int jc = j0 + c0;
            float t0 = (jc     <= qlo) ? acc[ma][na][0] * C : -1000.0f;
            float t1 = (jc + 1 <= qlo) ? acc[ma][na][1] * C : -1000.0f;
            float t2 = (jc     <= qhi) ? acc[ma][na][2] * C : -1000.0f;
            float t3 = (jc + 1 <= qhi) ? acc[ma][na][3] * C : -1000.0f;
            *(uint32_t*)&stage[r0*136 + c0]     = exp2h2(t0, t1);
            *(uint32_t*)&stage[(r0+8)*136 + c0] = exp2h2(t2, t3);
        }
    }
    __syncthreads();

    // E write (coalesced uint4) from stage
    {
        const int r = tid >> 1, h = tid & 1;
        const uint4* src = (const uint4*)(smem + r*272 + h*128);
        uint4* dst = (uint4*)(g_E + (size_t)(b * Sc + q0 + r) * Sc + j0 + h*64);
        #pragma unroll
        for (int k = 0; k < 8; k++) dst[k] = src[k];
    }
    // column sums -> denom (all 256 threads: col x row-half)
    {
        const int col = tid & 127, rh = tid >> 7;
        float s = 0.0f;
        #pragma unroll 8
        for (int r = rh*64; r < rh*64 + 64; r++)
            s += __half2float(stage[r*136 + col]);
        atomicAdd(&g_denom[b * Sc + j0 + col], s);
    }
}

// ---------------- kernel 3: vprep  Vt = fp16((V/denom)^T) ------------------
__global__ __launch_bounds__(256) void vprep_kernel() {
    __shared__ float tile[32][133];
    __shared__ float invs[32];
    const int b = blockIdx.y, s0 = blockIdx.x * 32, tid = threadIdx.x;
    if (tid < 32) invs[tid] = 1.0f / g_denom[b * Sc + s0 + tid];
    __syncthreads();
    #pragma unroll
    for (int i = 0; i < 16; i++) {
        int idx = tid + i * 256;
        int r = idx >> 7, c = idx & 127;
        tile[r][c] = g_Vp[(size_t)(b * Sc + s0 + r) * Vc + c] * invs[r];
    }
    __syncthreads();
    const int v = tid >> 1, h = tid & 1;
    uint32_t packs[8];
    #pragma unroll
    for (int k = 0; k < 8; k++)
        packs[k] = pack_h(__float2half(tile[h*16 + 2*k][v]),
                          __float2half(tile[h*16 + 2*k + 1][v]));
    uint4* dst = (uint4*)(g_Vt + (size_t)(b * Vc + v) * Sc + s0 + h*16);
    dst[0] = ((uint4*)packs)[0];
    dst[1] = ((uint4*)packs)[1];
}

// ---------------- kernel 4: concat (MLP-16 grid-stride) --------------------
__global__ __launch_bounds__(256) void concat_kernel(const float* __restrict__ x,
                                                     float* __restrict__ out) {
    const int base = blockIdx.x * 256 + threadIdx.x;    // 0..65535
    #pragma unroll
    for (int i = 0; i < 16; i++) {
        int idx = base + i * 65536;                     // float4 index
        int c4 = idx & 63;
        int t = idx >> 6;
        float4 v = make_float4(0.f, 0.f, 0.f, 0.f);
        if (c4 < 32) v = ((const float4*)x)[(size_t)t * 32 + c4];
        ((float4*)out)[idx] = v;
    }
}

// ---------------- kernel 5: attn (mma f16) ---------------------------------
#define AT_ES 0
#define AT_VH 34816
#define AT_SMEM 69632

__global__ __launch_bounds__(256) void attn_kernel(float* __restrict__ out) {
    extern __shared__ char smem[];
    const uint32_t sb = smem_u32(smem);
    const int tid = threadIdx.x;
    const int wid = tid >> 5, lane = tid & 31;
    const int grp = lane >> 2, qr = lane & 3;
    const int wm = wid >> 1, wn = wid & 1;
    const int b = blockIdx.y;

    int lin = blockIdx.x, qt = 0, base = 0;
    for (;;) { int gq = (qt + 8) >> 3; if (lin < base + gq) break; base += gq; qt++; }
    const int g0 = (lin - base) * 8;
    const int g1 = min(qt + 1, g0 + 8);
    const int q0 = qt * 128;

    float acc[2][8][4] = {};
    const uint32_t aBase = sb + AT_ES + (wm*32 + (lane & 15))*272 + (lane >> 4)*16;
    const uint32_t bBase = sb + AT_VH + (wn*64 + (lane & 15))*272 + (lane >> 4)*16;

    for (int jt = g0; jt < g1; jt++) {
        const int j0 = jt * 128;
        for (int idx = tid; idx < 2048; idx += 256) {
            int r = idx >> 4, ch = idx & 15;
            CP16(sb + AT_ES + r*272 + ch*16,
                 (const char*)g_E + ((size_t)(b*Sc + q0 + r)*Sc + j0)*2 + ch*16);
            CP16(sb + AT_VH + r*272 + ch*16,
                 (const char*)g_Vt + ((size_t)(b*Vc + r)*Sc + j0)*2 + ch*16);
        }
        CP_WAIT();
        __syncthreads();

        #pragma unroll
        for (int ks = 0; ks < 8; ks++) {
            const uint32_t kOff = (uint32_t)(ks * 32);
            uint32_t afr[2][4];
            #pragma unroll
            for (int ma = 0; ma < 2; ma++)
                LDM_X4(afr[ma][0], afr[ma][1], afr[ma][2], afr[ma][3],
                       aBase + ma*16*272 + kOff);
            uint32_t bfr[8][2];
            #pragma unroll
            for (int ng = 0; ng < 4; ng++) {
                uint32_t d0, d1, d2, d3;
                LDM_X4(d0, d1, d2, d3, bBase + ng*16*272 + kOff);
                bfr[2*ng][0]   = d0; bfr[2*ng][1]   = d2;
                bfr[2*ng+1][0] = d1; bfr[2*ng+1][1] = d3;
            }
            #pragma unroll
            for (int ma = 0; ma < 2; ma++)
                #pragma unroll
                for (int na = 0; na < 8; na++)
                    mma_f16(acc[ma][na], afr[ma], bfr[na]);
        }
        __syncthreads();
    }

    #pragma unroll
    for (int ma = 0; ma < 2; ma++) {
        const int r0 = q0 + wm*32 + ma*16 + grp;
        #pragma unroll
        for (int na = 0; na < 8; na++) {
            const int v0 = wn*64 + na*8 + qr*2;
            atomicAdd(&out[(size_t)(b*Sc + r0)*OUTC + Dc + v0],     acc[ma][na][0]);
            atomicAdd(&out[(size_t)(b*Sc + r0)*OUTC + Dc + v0 + 1], acc[ma][na][1]);
            atomicAdd(&out[(size_t)(b*Sc + r0 + 8)*OUTC + Dc + v0],     acc[ma][na][2]);
            atomicAdd(&out[(size_t)(b*Sc + r0 + 8)*OUTC + Dc + v0 + 1], acc[ma][na][3]);
        }
    }
}

// ---------------- launch ----------------
extern "C" void kernel_launch(void* const* d_in, const int* in_sizes, int n_in,
                              void* d_out, int out_size) {
    const float* x  = (const float*)d_in[0];
    const float* Wq = (const float*)d_in[1];
    const float* bq = (const float*)d_in[2];
    const float* Wk = (const float*)d_in[3];
    const float* bk = (const float*)d_in[4];
    const float* Wv = (const float*)d_in[5];
    const float* bv = (const float*)d_in[6];
    float* out = (float*)d_out;

    cudaFuncSetAttribute(proj_kernel,   cudaFuncAttributeMaxDynamicSharedMemorySize, PJ_SMEM);
    cudaFuncSetAttribute(scores_kernel, cudaFuncAttributeMaxDynamicSharedMemorySize, SC_SMEM);
    cudaFuncSetAttribute(attn_kernel,   cudaFuncAttributeMaxDynamicSharedMemorySize, AT_SMEM);

    proj_kernel<<<dim3(BSc / 128, 2), 256, PJ_SMEM>>>(x, Wq, bq, Wk, bk, Wv, bv);
    scores_kernel<<<dim3(528, Bc), 256, SC_SMEM>>>();
    vprep_kernel<<<dim3(Sc / 32, Bc), 256>>>();
    concat_kernel<<<256, 256>>>(x, out);
    attn_kernel<<<dim3(80, Bc), 256, AT_SMEM>>>(out);
}

// round 8
// speedup vs baseline: 3.8487x; 1.0659x over previous
#include <cuda_runtime.h>
#include <cuda_bf16.h>
#include <cuda_fp16.h>
#include <cstdint>

#define Bc 4
#define Sc 4096
#define Dc 128
#define Kc 64
#define Vc 128
#define BSc (Bc*Sc)
#define OUTC 256

// ---------------- scratch ----------------
__device__ __nv_bfloat16 g_Qs[(size_t)BSc * 128];      // [hi64 | lo64] per token
__device__ __nv_bfloat16 g_Ks[(size_t)BSc * 128];
__device__ float         g_Vp[(size_t)BSc * Vc];
__device__ __half        g_E[(size_t)Bc * Sc * Sc];    // exp(scores), causal zeros
__device__ __half        g_Vt[(size_t)Bc * Vc * Sc];   // [b][v][s], V/denom, fp16
__device__ float         g_denom[BSc];

// ---------------- PTX helpers ----------------
__device__ __forceinline__ uint32_t smem_u32(const void* p) {
    uint32_t a;
    asm("{ .reg .u64 t; cvta.to.shared.u64 t, %1; cvt.u32.u64 %0, t; }" : "=r"(a) : "l"(p));
    return a;
}
#define CP16(dst, src) \
    asm volatile("cp.async.cg.shared.global [%0], [%1], 16;" :: "r"(dst), "l"(src))
#define CP_COMMIT() asm volatile("cp.async.commit_group;" ::: "memory")
#define CP_WAITG(n) asm volatile("cp.async.wait_group %0;" :: "n"(n) : "memory")
#define CP_WAIT_ALL() \
    asm volatile("cp.async.commit_group;\ncp.async.wait_group 0;" ::: "memory")
#define LDM_X4(d0, d1, d2, d3, a) \
    asm volatile("ldmatrix.sync.aligned.m8n8.x4.shared.b16 {%0,%1,%2,%3}, [%4];" \
        : "=r"(d0), "=r"(d1), "=r"(d2), "=r"(d3) : "r"(a))

__device__ __forceinline__ void mma_bf16(float* d, const uint32_t* a, const uint32_t* b) {
    asm volatile("mma.sync.aligned.m16n8k16.row.col.f32.bf16.bf16.f32 "
        "{%0,%1,%2,%3}, {%4,%5,%6,%7}, {%8,%9}, {%0,%1,%2,%3};"
        : "+f"(d[0]), "+f"(d[1]), "+f"(d[2]), "+f"(d[3])
        : "r"(a[0]), "r"(a[1]), "r"(a[2]), "r"(a[3]), "r"(b[0]), "r"(b[1]));
}
__device__ __forceinline__ void mma_f16(float* d, const uint32_t* a, const uint32_t* b) {
    asm volatile("mma.sync.aligned.m16n8k16.row.col.f32.f16.f16.f32 "
        "{%0,%1,%2,%3}, {%4,%5,%6,%7}, {%8,%9}, {%0,%1,%2,%3};"
        : "+f"(d[0]), "+f"(d[1]), "+f"(d[2]), "+f"(d[3])
        : "r"(a[0]), "r"(a[1]), "r"(a[2]), "r"(a[3]), "r"(b[0]), "r"(b[1]));
}
__device__ __forceinline__ uint32_t pack_h(__half a, __half b) {
    __half2 t; t.x = a; t.y = b;
    return *reinterpret_cast<uint32_t*>(&t);
}
__device__ __forceinline__ uint32_t pack_b(__nv_bfloat16 a, __nv_bfloat16 b) {
    __nv_bfloat162 t; t.x = a; t.y = b;
    return *reinterpret_cast<uint32_t*>(&t);
}

// exp(s/8) as 2^(s*C): ex2.approx.f16x2 + fp32 residual correction.
__device__ __forceinline__ uint32_t exp2h2(float t0, float t1) {
    __half2 th = __floats2half2_rn(t0, t1);
    uint32_t thu = *reinterpret_cast<uint32_t*>(&th);
    uint32_t eu;
    asm("ex2.approx.f16x2 %0, %1;" : "=r"(eu) : "r"(thu));
    float tl0 = t0 - __half2float(__low2half(th));
    float tl1 = t1 - __half2float(__high2half(th));
    __half2 c = __floats2half2_rn(fmaf(0.6931472f, tl0, 1.0f),
                                  fmaf(0.6931472f, tl1, 1.0f));
    __half2 e = *reinterpret_cast<__half2*>(&eu);
    e = __hmul2(e, c);
    return *reinterpret_cast<uint32_t*>(&e);
}

// causal (qt, group-of-8) decode, heaviest first; sum over qt of ceil((qt+1)/8) = 80
__device__ __forceinline__ void decode_qt(int bx, int& qt, int& g0, int& g1) {
    int lin = 79 - bx;
    int base = 0; qt = 0;
    for (;;) { int gq = (qt + 8) >> 3; if (lin < base + gq) break; base += gq; qt++; }
    g0 = (lin - base) * 8;
    g1 = min(qt + 1, g0 + 8);
}

// ---------------- kernel 1: projections (mma split-bf16) -------------------
#define PJ_A0 0
#define PJ_A1 34816
#define PJ_B0 69632
#define PJ_B1 104448
#define PJ_BIAS 139264
#define PJ_SMEM 139776

__global__ __launch_bounds__(256) void proj_kernel(
    const float* __restrict__ x,
    const float* __restrict__ Wq, const float* __restrict__ bq,
    const float* __restrict__ Wk, const float* __restrict__ bk,
    const float* __restrict__ Wv, const float* __restrict__ bv) {
    extern __shared__ char smem[];
    const uint32_t sb = smem_u32(smem);
    const int tid = threadIdx.x;
    const int wid = tid >> 5, lane = tid & 31;
    const int grp = lane >> 2, qr = lane & 3;
    const int wm = wid >> 1, wn = wid & 1;
    const int nh = blockIdx.y;
    const int t0 = blockIdx.x * 128;

    if (nh == 0) {
        int i = blockIdx.x * 256 + tid;
        if (i < BSc) g_denom[i] = 0.0f;
    }
    if (tid < 128) {
        float bvv = (nh == 0) ? ((tid < 64) ? bq[tid] : bk[tid - 64]) : bv[tid];
        ((float*)(smem + PJ_BIAS))[tid] = bvv;
    }

    #pragma unroll
    for (int i = 0; i < 16; i++) {
        int idx = tid + i * 256;
        int r = idx >> 5, c4 = idx & 31;
        int ch = c4 >> 4, cc = c4 & 15;
        float4 a = *(const float4*)&x[(size_t)(t0 + r) * 128 + c4 * 4];
        __nv_bfloat16 h0 = __float2bfloat16(a.x), h1 = __float2bfloat16(a.y);
        __nv_bfloat16 h2 = __float2bfloat16(a.z), h3 = __float2bfloat16(a.w);
        uint2 hi = make_uint2(pack_b(h0, h1), pack_b(h2, h3));
        uint2 lo = make_uint2(
            pack_b(__float2bfloat16(a.x - __bfloat162float(h0)),
                   __float2bfloat16(a.y - __bfloat162float(h1))),
            pack_b(__float2bfloat16(a.z - __bfloat162float(h2)),
                   __float2bfloat16(a.w - __bfloat162float(h3))));
        char* ab = smem + (ch ? PJ_A1 : PJ_A0) + r * 272 + cc * 8;
        *(uint2*)ab = hi;
        *(uint2*)(ab + 128) = lo;

        const float* wsrc = (nh == 0)
            ? ((r < 64) ? (Wq + (size_t)r * 128) : (Wk + (size_t)(r - 64) * 128))
            : (Wv + (size_t)r * 128);
        float4 w = *(const float4*)&wsrc[c4 * 4];
        __nv_bfloat16 g0 = __float2bfloat16(w.x), g1 = __float2bfloat16(w.y);
        __nv_bfloat16 g2 = __float2bfloat16(w.z), g3 = __float2bfloat16(w.w);
        uint2 whi = make_uint2(pack_b(g0, g1), pack_b(g2, g3));
        uint2 wlo = make_uint2(
            pack_b(__float2bfloat16(w.x - __bfloat162float(g0)),
                   __float2bfloat16(w.y - __bfloat162float(g1))),
            pack_b(__float2bfloat16(w.z - __bfloat162float(g2)),
                   __float2bfloat16(w.w - __bfloat162float(g3))));
        char* bb = smem + (ch ? PJ_B1 : PJ_B0) + r * 272 + cc * 8;
        *(uint2*)bb = whi;
        *(uint2*)(bb + 128) = wlo;
    }
    __syncthreads();

    float acc[2][8][4] = {};
    const uint32_t aBase = sb + PJ_A0 + (wm*32 + (lane & 15))*272 + (lane >> 4)*16;
    const uint32_t bBase = sb + PJ_B0 + (wn*64 + (lane & 15))*272 + (lane >> 4)*16;
    const int aT[3] = {0, 1, 0}, bT[3] = {0, 0, 1};

    #pragma unroll
    for (int ch = 0; ch < 2; ch++) {
        #pragma unroll
        for (int t = 0; t < 3; t++) {
            #pragma unroll
            for (int ks = 0; ks < 4; ks++) {
                const uint32_t aOff = (uint32_t)(ch*34816 + aT[t]*128 + ks*32);
                const uint32_t bOff = (uint32_t)(ch*34816 + bT[t]*128 + ks*32);
                uint32_t afr[2][4];
                #pragma unroll
                for (int ma = 0; ma < 2; ma++)
                    LDM_X4(afr[ma][0], afr[ma][1], afr[ma][2], afr[ma][3],
                           aBase + ma*16*272 + aOff);
                uint32_t bfr[8][2];
                #pragma unroll
                for (int ng = 0; ng < 4; ng++) {
                    uint32_t d0, d1, d2, d3;
                    LDM_X4(d0, d1, d2, d3, bBase + ng*16*272 + bOff);
                    bfr[2*ng][0]   = d0; bfr[2*ng][1]   = d2;
                    bfr[2*ng+1][0] = d1; bfr[2*ng+1][1] = d3;
                }
                #pragma unroll
                for (int ma = 0; ma < 2; ma++)
                    #pragma unroll
                    for (int na = 0; na < 8; na++)
                        mma_bf16(acc[ma][na], afr[ma], bfr[na]);
            }
        }
    }
    __syncthreads();

    float* stage = (float*)smem;                 // [128][136]
    const float* biasS = (const float*)(smem + PJ_BIAS);
    #pragma unroll
    for (int ma = 0; ma < 2; ma++) {
        const int r0 = wm*32 + ma*16 + grp;
        #pragma unroll
        for (int na = 0; na < 8; na++) {
            const int c0 = wn*64 + na*8 + qr*2;
            stage[r0*136 + c0]     = acc[ma][na][0] + biasS[c0];
            stage[r0*136 + c0 + 1] = acc[ma][na][1] + biasS[c0 + 1];
            stage[(r0+8)*136 + c0]     = acc[ma][na][2] + biasS[c0];
            stage[(r0+8)*136 + c0 + 1] = acc[ma][na][3] + biasS[c0 + 1];
        }
    }
    __syncthreads();

    const int r = tid >> 1, h = tid & 1;
    if (nh == 0) {
        uint32_t hp[32], lp[32];
        #pragma unroll
        for (int k = 0; k < 32; k++) {
            float v0 = stage[r*136 + h*64 + 2*k];
            float v1 = stage[r*136 + h*64 + 2*k + 1];
            __nv_bfloat16 b0 = __float2bfloat16(v0), b1 = __float2bfloat16(v1);
            hp[k] = pack_b(b0, b1);
            lp[k] = pack_b(__float2bfloat16(v0 - __bfloat162float(b0)),
                           __float2bfloat16(v1 - __bfloat162float(b1)));
        }
        __nv_bfloat16* dstrow = (h == 0 ? g_Qs : g_Ks) + (size_t)(t0 + r) * 128;
        uint4* dh = (uint4*)dstrow;
        uint4* dl = (uint4*)(dstrow + 64);
        #pragma unroll
        for (int k = 0; k < 8; k++) { dh[k] = ((uint4*)hp)[k]; dl[k] = ((uint4*)lp)[k]; }
    } else {
        #pragma unroll
        for (int k = 0; k < 16; k++) {
            float4 v = *(const float4*)&stage[r*136 + h*64 + 4*k];
            *(float4*)&g_Vp[(size_t)(t0 + r) * 128 + h*64 + 4*k] = v;
        }
    }
}

// ---------------- kernel 2: scores (pipelined, Q-resident) -----------------
// grid (80, 4). Q tile resident; K tiles double-buffered; loop over <=8 j-tiles.
#define SCQ 0
#define SCK0 34816
#define SCK1 69632
#define SCST 104448
#define SC_SMEM 139264

__global__ __launch_bounds__(256) void scores_kernel() {
    extern __shared__ char smem[];
    const uint32_t sb = smem_u32(smem);
    const int tid = threadIdx.x;
    const int wid = tid >> 5, lane = tid & 31;
    const int grp = lane >> 2, qr = lane & 3;
    const int wm = wid >> 1, wn = wid & 1;
    const int b = blockIdx.y;

    int qt, g0, g1;
    decode_qt(blockIdx.x, qt, g0, g1);
    const int nk = g1 - g0;
    const int q0 = qt * 128;

    const char* Qsrc = (const char*)(g_Qs + (size_t)(b * Sc + q0) * 128);
    const char* Kbase = (const char*)(g_Ks + (size_t)b * Sc * 128);

    // initial fill: Q + K[0] (one group)
    for (int idx = tid; idx < 2048; idx += 256) {
        int r = idx >> 4, ch = idx & 15;
        CP16(sb + SCQ + r*272 + ch*16, Qsrc + r*256 + ch*16);
        CP16(sb + SCK0 + r*272 + ch*16, Kbase + (size_t)(g0*128 + r)*256 + ch*16);
    }
    CP_COMMIT();

    const uint32_t aBase = sb + SCQ + (wm*32 + (lane & 15))*272 + (lane >> 4)*16;
    const uint32_t lmRow = (uint32_t)((wn*64 + (lane & 15))*272 + (lane >> 4)*16);
    const int aT[3] = {0, 1, 0}, bT[3] = {0, 0, 1};
    const float C = 0.18033688011112042f;   // 0.125 * log2(e)
    __half* stage = (__half*)(smem + SCST); // [128][136]

    for (int i = 0; i < nk; i++) {
        const uint32_t kbuf = (i & 1) ? SCK1 : SCK0;
        if (i + 1 < nk) {
            const uint32_t nbuf = ((i + 1) & 1) ? SCK1 : SCK0;
            const size_t joff = (size_t)((g0 + i + 1) * 128) * 256;
            for (int idx = tid; idx < 2048; idx += 256) {
                int r = idx >> 4, ch = idx & 15;
                CP16(sb + nbuf + r*272 + ch*16, Kbase + joff + r*256 + ch*16);
            }
            CP_COMMIT();
            CP_WAITG(1);
        } else {
            CP_WAITG(0);
        }
        __syncthreads();

        float acc[2][8][4] = {};
        const uint32_t bBase = sb + kbuf + lmRow;
        #pragma unroll
        for (int t = 0; t < 3; t++) {
            #pragma unroll
            for (int ks = 0; ks < 4; ks++) {
                const uint32_t aOff = (uint32_t)(aT[t]*128 + ks*32);
                const uint32_t bOff = (uint32_t)(bT[t]*128 + ks*32);
                uint32_t afr[2][4];
                #pragma unroll
                for (int ma = 0; ma < 2; ma++)
                    LDM_X4(afr[ma][0], afr[ma][1], afr[ma][2], afr[ma][3],
                           aBase + ma*16*272 + aOff);
                uint32_t bfr[8][2];
                #pragma unroll
                for (int ng = 0; ng < 4; ng++) {
                    uint32_t d0, d1, d2, d3;
                    LDM_X4(d0, d1, d2, d3, bBase + ng*16*272 + bOff);
                    bfr[2*ng][0]   = d0; bfr[2*ng][1]   = d2;
                    bfr[2*ng+1][0] = d1; bfr[2*ng+1][1] = d3;
                }
                #pragma unroll
                for (int ma = 0; ma < 2; ma++)
                    #pragma unroll
                    for (int na = 0; na < 8; na++)
                        mma_bf16(acc[ma][na], afr[ma], bfr[na]);
            }
        }

        // epilogue: exp -> stage
        const int j0 = (g0 + i) * 128;
        #pragma unroll
        for (int ma = 0; ma < 2; ma++) {
            const int r0 = wm*32 + ma*16 + grp;
            const int qlo = q0 + r0, qhi = qlo + 8;
            #pragma unroll
            for (int na = 0; na < 8; na++) {
                const int c0 = wn*64 + na*8 + qr*2;
                const int jc = j0 + c0;
                float t0 = (jc     <= qlo) ? acc[ma][na][0] * C : -1000.0f;
                float t1 = (jc + 1 <= qlo) ? acc[ma][na][1] * C : -1000.0f;
                float t2 = (jc     <= qhi) ? acc[ma][na][2] * C : -1000.0f;
                float t3 = (jc + 1 <= qhi) ? acc[ma][na][3] * C : -1000.0f;
                *(uint32_t*)&stage[r0*136 + c0]     = exp2h2(t0, t1);
                *(uint32_t*)&stage[(r0+8)*136 + c0] = exp2h2(t2, t3);
            }
        }
        __syncthreads();

        // E write + column sums
        {
            const int r = tid >> 1, h = tid & 1;
            const uint4* src = (const uint4*)((char*)stage + r*272 + h*128);
            uint4* dst = (uint4*)(g_E + (size_t)(b * Sc + q0 + r) * Sc + j0 + h*64);
            #pragma unroll
            for (int k = 0; k < 8; k++) dst[k] = src[k];
        }
        {
            const int col = tid & 127, rh = tid >> 7;
            float s = 0.0f;
            #pragma unroll 8
            for (int r = rh*64; r < rh*64 + 64; r++)
                s += __half2float(stage[r*136 + col]);
            atomicAdd(&g_denom[b * Sc + j0 + col], s);
        }
        __syncthreads();
    }
}

// ---------------- kernel 3: vprep ----------------
__global__ __launch_bounds__(256) void vprep_kernel() {
    __shared__ float tile[32][133];
    __shared__ float invs[32];
    const int b = blockIdx.y, s0 = blockIdx.x * 32, tid = threadIdx.x;
    if (tid < 32) invs[tid] = 1.0f / g_denom[b * Sc + s0 + tid];
    __syncthreads();
    #pragma unroll
    for (int i = 0; i < 16; i++) {
        int idx = tid + i * 256;
        int r = idx >> 7, c = idx & 127;
        tile[r][c] = g_Vp[(size_t)(b * Sc + s0 + r) * Vc + c] * invs[r];
    }
    __syncthreads();
    const int v = tid >> 1, h = tid & 1;
    uint32_t packs[8];
    #pragma unroll
    for (int k = 0; k < 8; k++)
        packs[k] = pack_h(__float2half(tile[h*16 + 2*k][v]),
                          __float2half(tile[h*16 + 2*k + 1][v]));
    uint4* dst = (uint4*)(g_Vt + (size_t)(b * Vc + v) * Sc + s0 + h*16);
    dst[0] = ((uint4*)packs)[0];
    dst[1] = ((uint4*)packs)[1];
}

// ---------------- kernel 4: concat ----------------
__global__ __launch_bounds__(256) void concat_kernel(const float* __restrict__ x,
                                                     float* __restrict__ out) {
    const int base = blockIdx.x * 256 + threadIdx.x;
    #pragma unroll
    for (int i = 0; i < 16; i++) {
        int idx = base + i * 65536;
        int c4 = idx & 63;
        int t = idx >> 6;
        float4 v = make_float4(0.f, 0.f, 0.f, 0.f);
        if (c4 < 32) v = ((const float4*)x)[(size_t)t * 32 + c4];
        ((float4*)out)[idx] = v;
    }
}

// ---------------- kernel 5: attn (pipelined double-buffer) -----------------
#define AE0 0
#define AV0 34816
#define AE1 69632
#define AV1 104448
#define AT_SMEM 139264

__global__ __launch_bounds__(256) void attn_kernel(float* __restrict__ out) {
    extern __shared__ char smem[];
    const uint32_t sb = smem_u32(smem);
    const int tid = threadIdx.x;
    const int wid = tid >> 5, lane = tid & 31;
    const int grp = lane >> 2, qr = lane & 3;
    const int wm = wid >> 1, wn = wid & 1;
    const int b = blockIdx.y;

    int qt, g0, g1;
    decode_qt(blockIdx.x, qt, g0, g1);
    const int nk = g1 - g0;
    const int q0 = qt * 128;

    const char* Ebase = (const char*)g_E + (size_t)(b*Sc + q0) * Sc * 2;
    const char* Vbase = (const char*)g_Vt + (size_t)b * Vc * Sc * 2;

    // initial fill: E[0] + V[0]
    for (int idx = tid; idx < 2048; idx += 256) {
        int r = idx >> 4, ch = idx & 15;
        CP16(sb + AE0 + r*272 + ch*16, Ebase + (size_t)r*Sc*2 + g0*256 + ch*16);
        CP16(sb + AV0 + r*272 + ch*16, Vbase + (size_t)r*Sc*2 + g0*256 + ch*16);
    }
    CP_COMMIT();

    float acc[2][8][4] = {};
    const uint32_t lmA = (uint32_t)((wm*32 + (lane & 15))*272 + (lane >> 4)*16);
    const uint32_t lmB = (uint32_t)((wn*64 + (lane & 15))*272 + (lane >> 4)*16);

    for (int i = 0; i < nk; i++) {
        const uint32_t ebuf = (i & 1) ? AE1 : AE0;
        const uint32_t vbuf = (i & 1) ? AV1 : AV0;
        if (i + 1 < nk) {
            const uint32_t ne = ((i + 1) & 1) ? AE1 : AE0;
            const uint32_t nv = ((i + 1) & 1) ? AV1 : AV0;
            const int jcol = (g0 + i + 1) * 256;
            for (int idx = tid; idx < 2048; idx += 256) {
                int r = idx >> 4, ch = idx & 15;
                CP16(sb + ne + r*272 + ch*16, Ebase + (size_t)r*Sc*2 + jcol + ch*16);
                CP16(sb + nv + r*272 + ch*16, Vbase + (size_t)r*Sc*2 + jcol + ch*16);
            }
            CP_COMMIT();
            CP_WAITG(1);
        } else {
            CP_WAITG(0);
        }
        __syncthreads();

        const uint32_t aBase = sb + ebuf + lmA;
        const uint32_t bBase = sb + vbuf + lmB;
        #pragma unroll
        for (int ks = 0; ks < 8; ks++) {
            const uint32_t kOff = (uint32_t)(ks * 32);
            uint32_t afr[2][4];
            #pragma unroll
            for (int ma = 0; ma < 2; ma++)
                LDM_X4(afr[ma][0], afr[ma][1], afr[ma][2], afr[ma][3],
                       aBase + ma*16*272 + kOff);
            uint32_t bfr[8][2];
            #pragma unroll
            for (int ng = 0; ng < 4; ng++) {
                uint32_t d0, d1, d2, d3;
                LDM_X4(d0, d1, d2, d3, bBase + ng*16*272 + kOff);
                bfr[2*ng][0]   = d0; bfr[2*ng][1]   = d2;
                bfr[2*ng+1][0] = d1; bfr[2*ng+1][1] = d3;
            }
            #pragma unroll
            for (int ma = 0; ma < 2; ma++)
                #pragma unroll
                for (int na = 0; na < 8; na++)
                    mma_f16(acc[ma][na], afr[ma], bfr[na]);
        }
        __syncthreads();
    }

    #pragma unroll
    for (int ma = 0; ma < 2; ma++) {
        const int r0 = q0 + wm*32 + ma*16 + grp;
        #pragma unroll
        for (int na = 0; na < 8; na++) {
            const int v0 = wn*64 + na*8 + qr*2;
            atomicAdd(&out[(size_t)(b*Sc + r0)*OUTC + Dc + v0],     acc[ma][na][0]);
            atomicAdd(&out[(size_t)(b*Sc + r0)*OUTC + Dc + v0 + 1], acc[ma][na][1]);
            atomicAdd(&out[(size_t)(b*Sc + r0 + 8)*OUTC + Dc + v0],     acc[ma][na][2]);
            atomicAdd(&out[(size_t)(b*Sc + r0 + 8)*OUTC + Dc + v0 + 1], acc[ma][na][3]);
        }
    }
}

// ---------------- launch ----------------
extern "C" void kernel_launch(void* const* d_in, const int* in_sizes, int n_in,
                              void* d_out, int out_size) {
    const float* x  = (const float*)d_in[0];
    const float* Wq = (const float*)d_in[1];
    const float* bq = (const float*)d_in[2];
    const float* Wk = (const float*)d_in[3];
    const float* bk = (const float*)d_in[4];
    const float* Wv = (const float*)d_in[5];
    const float* bv = (const float*)d_in[6];
    float* out = (float*)d_out;

    cudaFuncSetAttribute(proj_kernel,   cudaFuncAttributeMaxDynamicSharedMemorySize, PJ_SMEM);
    cudaFuncSetAttribute(scores_kernel, cudaFuncAttributeMaxDynamicSharedMemorySize, SC_SMEM);
    cudaFuncSetAttribute(attn_kernel,   cudaFuncAttributeMaxDynamicSharedMemorySize, AT_SMEM);

    proj_kernel<<<dim3(BSc / 128, 2), 256, PJ_SMEM>>>(x, Wq, bq, Wk, bk, Wv, bv);
    scores_kernel<<<dim3(80, Bc), 256, SC_SMEM>>>();
    vprep_kernel<<<dim3(Sc / 32, Bc), 256>>>();
    concat_kernel<<<256, 256>>>(x, out);
    attn_kernel<<<dim3(80, Bc), 256, AT_SMEM>>>(out);
}